// round 12
// baseline (speedup 1.0000x reference)
#include <cuda_runtime.h>
#include <cuda_bf16.h>
#include <cstdint>

#define NB 256      // batch
#define M 128       // txt positions (j), compacted to NJ real
#define N 128       // img positions (i), compacted to NI real
#define D 1024      // embedding dim
#define NTHREADS 256
#define KBLK 32                   // k-values per tile block (32 bf16 = 64B row)
#define NBLKS (D / KBLK)          // 32
#define TILE_B (128 * 64)         // 8KB per matrix per buffer

typedef unsigned long long u64;

__device__ float g_dist[NB];
__device__ unsigned int g_count = 0;

// ------------------------- helpers -------------------------
__device__ __forceinline__ uint32_t smem_u32(const void* p) {
    uint32_t a;
    asm("{ .reg .u64 t; cvta.to.shared.u64 t, %1; cvt.u32.u64 %0, t; }"
        : "=r"(a) : "l"(p));
    return a;
}
#define SWZ64(o) ((o) ^ ((((uint32_t)(o)) >> 3) & 0x30))

__device__ __forceinline__ uint32_t cvt2(float a, float b) {
    __nv_bfloat162 p = __float22bfloat162_rn(make_float2(a, b));
    return *reinterpret_cast<uint32_t*>(&p);
}
__device__ __forceinline__ float fast_exp(float x) {
    float y;
    asm("ex2.approx.f32 %0, %1;" : "=f"(y) : "f"(x * 1.4426950408889634f));
    return y;
}
__device__ __forceinline__ float frcp(float x) {
    float y;
    asm("rcp.approx.f32 %0, %1;" : "=f"(y) : "f"(x));
    return y;
}
__device__ __forceinline__ void ldsm_x4(uint32_t addr, uint32_t& r0, uint32_t& r1,
                                        uint32_t& r2, uint32_t& r3) {
    asm volatile("ldmatrix.sync.aligned.m8n8.x4.shared.b16 {%0,%1,%2,%3}, [%4];"
                 : "=r"(r0), "=r"(r1), "=r"(r2), "=r"(r3) : "r"(addr));
}
__device__ __forceinline__ void mma16816(float* c, uint32_t a0, uint32_t a1,
                                         uint32_t a2, uint32_t a3,
                                         uint32_t b0, uint32_t b1) {
    asm volatile(
        "mma.sync.aligned.m16n8k16.row.col.f32.bf16.bf16.f32 "
        "{%0,%1,%2,%3}, {%4,%5,%6,%7}, {%8,%9}, {%0,%1,%2,%3};"
        : "+f"(c[0]), "+f"(c[1]), "+f"(c[2]), "+f"(c[3])
        : "r"(a0), "r"(a1), "r"(a2), "r"(a3), "r"(b0), "r"(b1));
}

// ---- packed f32x2 (sm_100+ base ISA) ----
__device__ __forceinline__ u64 pack2(float x, float y) {
    u64 r; asm("mov.b64 %0, {%1, %2};" : "=l"(r) : "f"(x), "f"(y)); return r;
}
__device__ __forceinline__ float2 unpack2(u64 v) {
    float2 r; asm("mov.b64 {%0, %1}, %2;" : "=f"(r.x), "=f"(r.y) : "l"(v)); return r;
}
__device__ __forceinline__ u64 mul2(u64 a, u64 b) {
    u64 d; asm("mul.rn.f32x2 %0, %1, %2;" : "=l"(d) : "l"(a), "l"(b)); return d;
}
__device__ __forceinline__ u64 fma2_(u64 a, u64 b, u64 c) {
    u64 d; asm("fma.rn.f32x2 %0, %1, %2, %3;" : "=l"(d) : "l"(a), "l"(b), "l"(c)); return d;
}

union F4U2 { float4 f4; u64 u2[2]; };

// convert + ss-accumulate + store one 16-float slot half
__device__ __forceinline__ void slot_emit(const float4* v, u64& ss2,
                                          char* bb, uint32_t da, uint32_t db) {
    F4U2 u0, u1, u2, u3;
    u0.f4 = v[0]; u1.f4 = v[1]; u2.f4 = v[2]; u3.f4 = v[3];
    ss2 = fma2_(u0.u2[0], u0.u2[0], ss2);
    ss2 = fma2_(u0.u2[1], u0.u2[1], ss2);
    ss2 = fma2_(u1.u2[0], u1.u2[0], ss2);
    ss2 = fma2_(u1.u2[1], u1.u2[1], ss2);
    ss2 = fma2_(u2.u2[0], u2.u2[0], ss2);
    ss2 = fma2_(u2.u2[1], u2.u2[1], ss2);
    ss2 = fma2_(u3.u2[0], u3.u2[0], ss2);
    ss2 = fma2_(u3.u2[1], u3.u2[1], ss2);
    uint4 w0 = make_uint4(cvt2(v[0].x, v[0].y), cvt2(v[0].z, v[0].w),
                          cvt2(v[1].x, v[1].y), cvt2(v[1].z, v[1].w));
    uint4 w1 = make_uint4(cvt2(v[2].x, v[2].y), cvt2(v[2].z, v[2].w),
                          cvt2(v[3].x, v[3].y), cvt2(v[3].z, v[3].w));
    *reinterpret_cast<uint4*>(bb + da) = w0;
    *reinterpret_cast<uint4*>(bb + db) = w1;
}

// ownership-linear index (floats): thread (warp w, lane = jg + 16*ig)
// owns i = 2*w + ig + 16*ii (ii=0..7), j = jg*8 .. jg*8+7 (half = (j>>2)&1)
#define AIDX(w, ii, half, ig, jg) \
    ((((((w) * 8 + (ii)) * 2 + (half)) * 2 + (ig)) * 16 + (jg)) * 4)

struct ShMem {
    float As[N * M];        // 64KB ownership-linear A; GEMM k-tiles aliased inside
    float spartW[8][128];   // per-warp s_j partials; doubles as ssarr[512] pre-IPOT
    float spart[NTHREADS];
    float invx[M];
    float invy[N];
    float xmask[M];
    float sigma[M];
    int   idxj[M];
    int   idxi[N];
    int   NJ, NI;
    unsigned int tick;
};

extern __shared__ __align__(16) char smem_raw[];

__global__ __launch_bounds__(NTHREADS, 2)
void ot_kernel(const float* __restrict__ txt,
               const float* __restrict__ obj,
               const int* __restrict__ txt_num,
               const int* __restrict__ obj_num,
               float* __restrict__ out)
{
    ShMem* sh = reinterpret_cast<ShMem*>(smem_raw);
    const int tid  = threadIdx.x;
    const int lane = tid & 31;
    const int warp = tid >> 5;
    const int b    = blockIdx.x;

    const float* txt_b = txt + (size_t)b * M * D;
    const float* obj_b = obj + (size_t)b * M * D;

    // GEMM tiles aliased into the (not-yet-used) As region, 1024-aligned
    char* tbase = (char*)(((uintptr_t)sh->As + 1023) & ~(uintptr_t)1023);
    const uint32_t tbase_s = (smem_u32(sh->As) + 1023u) & ~1023u;

    // ---------------- Phase 0: compaction (ballot ranks) ----------------
    if (warp == 0) {
        int base = 0;
        #pragma unroll
        for (int c = 0; c < 4; ++c) {
            int j = c * 32 + lane;
            bool real = (txt_num[b * 128 + j] != 0);
            unsigned m = __ballot_sync(0xffffffffu, real);
            int rank = base + __popc(m & ((1u << lane) - 1u));
            if (real) sh->idxj[rank] = j;
            base += __popc(m);
        }
        if (lane == 0) sh->NJ = base;
    }
    if (warp == 1) {
        int base = 0;
        #pragma unroll
        for (int c = 0; c < 4; ++c) {
            int i = c * 32 + lane;
            bool real = (i < 127) && (obj_num[b * 128 + i + 1] != 0);
            unsigned m = __ballot_sync(0xffffffffu, real);
            int rank = base + __popc(m & ((1u << lane) - 1u));
            if (real) sh->idxi[rank] = i;
            base += __popc(m);
        }
        if (lane == 0) sh->NI = base;
    }
    __syncthreads();
    const int NJ = sh->NJ, NI = sh->NI;
    const int NR = NJ + NI;
    const float xlv = (float)NJ, ylv = (float)NI;
    if (tid < 128) sh->xmask[tid] = (tid < NJ) ? 0.f : 1e4f;

    // ---------------- Phase 1: GEMM loader (balanced combined rows) --------
    // slot0: combined row rc0 = tid>>1 (X rows [0,NJ), then Y rows);
    // slot1: rc1 = rc0+128 (live only when NR>128; always a Y row).
    const int seg = tid & 1;
    const int rc0 = tid >> 1;
    const int rc1 = rc0 + 128;
    const bool live0 = rc0 < NR;
    const bool live1 = rc1 < NR;
    const float* p0 = txt_b;
    const float* p1 = obj_b;
    uint32_t d0a = 0, d0b = 0, d1a = 0, d1b = 0;
    if (live0) {
        uint32_t off;
        if (rc0 < NJ) {
            p0 = txt_b + (size_t)sh->idxj[rc0] * D + seg * 16;
            off = (uint32_t)(rc0 * 64 + seg * 32);
        } else {
            p0 = obj_b + (size_t)(sh->idxi[rc0 - NJ] + 1) * D + seg * 16;
            off = (uint32_t)(TILE_B + (rc0 - NJ) * 64 + seg * 32);
        }
        d0a = (off & ~63u) | SWZ64(off & 63u);
        d0b = (off & ~63u) | SWZ64((off & 63u) + 16);
        // note: swizzle only touches bits 4..5 using bits 7..8 of the row offset:
        d0a = SWZ64(off); d0b = SWZ64(off + 16);
    }
    if (live1) {
        int i = rc1 - NJ;
        p1 = obj_b + (size_t)(sh->idxi[i] + 1) * D + seg * 16;
        uint32_t off = (uint32_t)(TILE_B + i * 64 + seg * 32);
        d1a = SWZ64(off); d1b = SWZ64(off + 16);
    }

    // MMA warp grid 2x4: wi -> 32 i-rows, wj -> 64 j-cols
    const int wi = warp >> 1;
    const int wj = warp & 1;
    const bool mma_act = (wi * 32 < NI) && (wj * 64 < NJ);
    float acc[2][4][2][4];
    #pragma unroll
    for (int mi = 0; mi < 2; ++mi)
        #pragma unroll
        for (int nb = 0; nb < 4; ++nb)
            #pragma unroll
            for (int q = 0; q < 2; ++q)
                #pragma unroll
                for (int c = 0; c < 4; ++c) acc[mi][nb][q][c] = 0.f;

    const uint32_t ro = (lane & 7) + (((lane >> 3) & 1) << 3);
    const uint32_t ch = (lane >> 4) << 4;

    float4 v0[4], v1[4];
    u64 ss2_0 = pack2(0.f, 0.f), ss2_1 = pack2(0.f, 0.f);
    if (live0) {
        const float4* s = reinterpret_cast<const float4*>(p0);
        #pragma unroll
        for (int q = 0; q < 4; ++q) v0[q] = s[q];
        p0 += KBLK;
    }
    if (live1) {
        const float4* s = reinterpret_cast<const float4*>(p1);
        #pragma unroll
        for (int q = 0; q < 4; ++q) v1[q] = s[q];
        p1 += KBLK;
    }

    for (int blk = 0; blk < NBLKS; ++blk) {
        const int buf = blk & 1;
        char* bb = tbase + buf * (2 * TILE_B);

        if (live0) slot_emit(v0, ss2_0, bb, d0a, d0b);
        if (live1) slot_emit(v1, ss2_1, bb, d1a, d1b);

        // prefetch next block before the barrier (overlaps with MMA)
        if (blk + 1 < NBLKS) {
            if (live0) {
                const float4* s = reinterpret_cast<const float4*>(p0);
                #pragma unroll
                for (int q = 0; q < 4; ++q) v0[q] = s[q];
                p0 += KBLK;
            }
            if (live1) {
                const float4* s = reinterpret_cast<const float4*>(p1);
                #pragma unroll
                for (int q = 0; q < 4; ++q) v1[q] = s[q];
                p1 += KBLK;
            }
        }
        __syncthreads();   // single barrier per block (buffer reuse distance = 2)

        if (mma_act) {
            const uint32_t xs = tbase_s + buf * (2 * TILE_B);
            const uint32_t ys = xs + TILE_B;
            #pragma unroll
            for (int s = 0; s < 2; ++s) {
                const uint32_t coff = (uint32_t)(s * 32) + ch;
                uint32_t a[2][4];
                #pragma unroll
                for (int mi = 0; mi < 2; ++mi)
                    ldsm_x4(ys + SWZ64((wi * 32 + mi * 16 + ro) * 64 + coff),
                            a[mi][0], a[mi][1], a[mi][2], a[mi][3]);
                #pragma unroll
                for (int nb = 0; nb < 4; ++nb) {
                    uint32_t r0, r1, r2, r3;
                    ldsm_x4(xs + SWZ64((wj * 64 + nb * 16 + ro) * 64 + coff),
                            r0, r1, r2, r3);
                    #pragma unroll
                    for (int mi = 0; mi < 2; ++mi) {
                        mma16816(acc[mi][nb][0], a[mi][0], a[mi][1], a[mi][2], a[mi][3], r0, r2);
                        mma16816(acc[mi][nb][1], a[mi][0], a[mi][1], a[mi][2], a[mi][3], r1, r3);
                    }
                }
            }
        }
    }
    __syncthreads();

    // ---------------- norms (per combined row) ----------------
    {
        float* ssarr = reinterpret_cast<float*>(sh->spartW);   // 512 floats
        float2 s0 = unpack2(ss2_0), s1 = unpack2(ss2_1);
        ssarr[tid]       = s0.x + s0.y;   // index = rc0*2 + seg == tid
        ssarr[256 + tid] = s1.x + s1.y;
        __syncthreads();
        if (tid < 128) { sh->invx[tid] = 0.f; sh->invy[tid] = 0.f; }
        __syncthreads();
        if (tid < 128) {
            #pragma unroll
            for (int h = 0; h < 2; ++h) {
                int r = tid + h * 128;
                if (r < NR) {
                    float s = ssarr[2 * r] + ssarr[2 * r + 1];
                    float inv = frcp(fmaxf(sqrtf(s), 1e-5f));
                    if (r < NJ) sh->invx[r] = inv;
                    else        sh->invy[r - NJ] = inv;
                }
            }
        }
        __syncthreads();
    }

    // ---------------- Epilogue: acc -> As (strided ownership layout) --------
    {
        const int r_ = lane >> 2;           // 0..7 = i mod 16 (low 8)
        const int cp = (lane & 3) * 2;
        const int we_lo = r_ >> 1;          // dest warp for row i0
        const int ig_e  = r_ & 1;
        #pragma unroll
        for (int mi = 0; mi < 2; ++mi) {
            const int i0 = wi * 32 + mi * 16 + r_;
            const int i1 = i0 + 8;
            const int ii_e = wi * 2 + mi;   // i>>4 for both rows
            const float iy0 = sh->invy[i0], iy1 = sh->invy[i1];
            #pragma unroll
            for (int nb = 0; nb < 4; ++nb) {
                #pragma unroll
                for (int q = 0; q < 2; ++q) {
                    const int j = wj * 64 + nb * 16 + q * 8 + cp;
                    const int jge = j >> 3, hfe = (j >> 2) & 1, ue = j & 3;
                    const float ix0 = sh->invx[j], ix1 = sh->invx[j + 1];
                    const float* c = acc[mi][nb][q];
                    float a00 = (i0 < NI && j     < NJ)
                              ? fast_exp(-2.f * (1.f - c[0] * iy0 * ix0)) : 0.f;
                    float a01 = (i0 < NI && j + 1 < NJ)
                              ? fast_exp(-2.f * (1.f - c[1] * iy0 * ix1)) : 0.f;
                    float a10 = (i1 < NI && j     < NJ)
                              ? fast_exp(-2.f * (1.f - c[2] * iy1 * ix0)) : 0.f;
                    float a11 = (i1 < NI && j + 1 < NJ)
                              ? fast_exp(-2.f * (1.f - c[3] * iy1 * ix1)) : 0.f;
                    *reinterpret_cast<float2*>(&sh->As[AIDX(we_lo,     ii_e, hfe, ig_e, jge) + ue])
                        = make_float2(a00, a01);
                    *reinterpret_cast<float2*>(&sh->As[AIDX(we_lo + 4, ii_e, hfe, ig_e, jge) + ue])
                        = make_float2(a10, a11);
                }
            }
        }
    }
    __syncthreads();

    // ---------------- Phase 2: IPOT, Q in regs, rows strided over all warps --
    const int jg = lane & 15;
    const int ig = lane >> 4;
    const int ibase = 2 * warp + ig;   // this thread's rows: ibase + 16*ii

    u64 q2[8][4];
    float ym_[8], d_[8];
    #pragma unroll
    for (int ii = 0; ii < 8; ++ii) {
        ym_[ii] = (ibase + 16 * ii < NI) ? 0.f : 1e4f;
        d_[ii] = 0.f;
        if (2 * warp + 16 * ii < NI) {   // warp-uniform liveness
            F4U2 u0, u1;
            u0.f4 = *reinterpret_cast<const float4*>(&sh->As[AIDX(warp, ii, 0, ig, jg)]);
            u1.f4 = *reinterpret_cast<const float4*>(&sh->As[AIDX(warp, ii, 1, ig, jg)]);
            q2[ii][0] = u0.u2[0]; q2[ii][1] = u0.u2[1];
            q2[ii][2] = u1.u2[0]; q2[ii][3] = u1.u2[1];
        } else {
            q2[ii][0] = q2[ii][1] = q2[ii][2] = q2[ii][3] = 0ull;
        }
    }

    if (tid < 128) sh->sigma[tid] = (tid < NJ) ? frcp(xlv) : 0.f;
    __syncthreads();

    u64 sg2[4];
    {
        F4U2 sa, sb;
        sa.f4 = *reinterpret_cast<const float4*>(&sh->sigma[jg * 8]);
        sb.f4 = *reinterpret_cast<const float4*>(&sh->sigma[jg * 8 + 4]);
        sg2[0] = sa.u2[0]; sg2[1] = sa.u2[1]; sg2[2] = sb.u2[0]; sg2[3] = sb.u2[1];
    }

    // delta_0 from r = Q.sigma0
    #pragma unroll
    for (int ii = 0; ii < 8; ++ii) {
        if (2 * warp + 16 * ii < NI) {
            u64 acc2 = mul2(q2[ii][0], sg2[0]);
            acc2 = fma2_(q2[ii][1], sg2[1], acc2);
            acc2 = fma2_(q2[ii][2], sg2[2], acc2);
            acc2 = fma2_(q2[ii][3], sg2[3], acc2);
            float2 pr = unpack2(acc2);
            float rv = pr.x + pr.y;
            #pragma unroll
            for (int o = 1; o < 16; o <<= 1) rv += __shfl_xor_sync(0xffffffffu, rv, o);
            d_[ii] = frcp(ylv * rv + ym_[ii]);
        }
    }

    for (int t = 0; t < 50; ++t) {
        // s_j partials from registers (all 8 warps contribute)
        u64 s2[4];
        #pragma unroll
        for (int p = 0; p < 4; ++p) s2[p] = pack2(0.f, 0.f);
        #pragma unroll
        for (int ii = 0; ii < 8; ++ii) {
            if (2 * warp + 16 * ii < NI) {
                u64 dd = pack2(d_[ii], d_[ii]);
                #pragma unroll
                for (int p = 0; p < 4; ++p) s2[p] = fma2_(q2[ii][p], dd, s2[p]);
            }
        }
        float s8[8];
        #pragma unroll
        for (int p = 0; p < 4; ++p) {
            float2 v = unpack2(s2[p]);
            s8[2 * p] = v.x; s8[2 * p + 1] = v.y;
        }
        #pragma unroll
        for (int e = 0; e < 8; ++e) s8[e] += __shfl_xor_sync(0xffffffffu, s8[e], 16);
        if (ig == 0) {
            *reinterpret_cast<float4*>(&sh->spartW[warp][jg * 8])
                = make_float4(s8[0], s8[1], s8[2], s8[3]);
            *reinterpret_cast<float4*>(&sh->spartW[warp][jg * 8 + 4])
                = make_float4(s8[4], s8[5], s8[6], s8[7]);
        }
        __syncthreads();
        if (tid < 128) {
            float s = 0.f;
            #pragma unroll
            for (int w8 = 0; w8 < 8; ++w8) s += sh->spartW[w8][tid];
            sh->sigma[tid] = frcp(xlv * s + sh->xmask[tid]);
        }
        __syncthreads();
        {
            F4U2 sa, sb;
            sa.f4 = *reinterpret_cast<const float4*>(&sh->sigma[jg * 8]);
            sb.f4 = *reinterpret_cast<const float4*>(&sh->sigma[jg * 8 + 4]);
            sg2[0] = sa.u2[0]; sg2[1] = sa.u2[1]; sg2[2] = sb.u2[0]; sg2[3] = sb.u2[1];
        }
        if (t < 49) {
            // Q <- A*delta*Q*sigma, fused with next r_i -> delta
            #pragma unroll
            for (int ii = 0; ii < 8; ++ii) {
                if (2 * warp + 16 * ii < NI) {
                    F4U2 a0, a1;
                    a0.f4 = *reinterpret_cast<const float4*>(&sh->As[AIDX(warp, ii, 0, ig, jg)]);
                    a1.f4 = *reinterpret_cast<const float4*>(&sh->As[AIDX(warp, ii, 1, ig, jg)]);
                    u64 av[4] = {a0.u2[0], a0.u2[1], a1.u2[0], a1.u2[1]};
                    u64 dd = pack2(d_[ii], d_[ii]);
                    u64 acc2 = pack2(0.f, 0.f);
                    #pragma unroll
                    for (int p = 0; p < 4; ++p) {
                        u64 f  = mul2(sg2[p], dd);
                        u64 tq = mul2(av[p], q2[ii][p]);
                        q2[ii][p] = mul2(tq, f);
                        acc2 = fma2_(q2[ii][p], sg2[p], acc2);
                    }
                    float2 pr = unpack2(acc2);
                    float rv = pr.x + pr.y;
                    #pragma unroll
                    for (int o = 1; o < 16; o <<= 1) rv += __shfl_xor_sync(0xffffffffu, rv, o);
                    d_[ii] = frcp(ylv * rv + ym_[ii]);
                }
            }
        }
    }

    // ---------------- Final: dist_b = sum cost * delta_i * Q * sigma_j --------
    float local = 0.f;
    #pragma unroll
    for (int ii = 0; ii < 8; ++ii) {
        if (2 * warp + 16 * ii < NI) {
            F4U2 a0, a1;
            a0.f4 = *reinterpret_cast<const float4*>(&sh->As[AIDX(warp, ii, 0, ig, jg)]);
            a1.f4 = *reinterpret_cast<const float4*>(&sh->As[AIDX(warp, ii, 1, ig, jg)]);
            u64 av[4] = {a0.u2[0], a0.u2[1], a1.u2[0], a1.u2[1]};
            const float dl = d_[ii];
            #pragma unroll
            for (int p = 0; p < 4; ++p) {
                float2 aa = unpack2(av[p]);
                float2 qq = unpack2(q2[ii][p]);
                float2 ss = unpack2(sg2[p]);
                if (aa.x > 0.f) local += (-0.5f * __logf(aa.x)) * dl * qq.x * ss.x;
                if (aa.y > 0.f) local += (-0.5f * __logf(aa.y)) * dl * qq.y * ss.y;
            }
        }
    }
    __syncthreads();
    sh->spart[tid] = local;
    __syncthreads();
    #pragma unroll
    for (int s = 128; s; s >>= 1) {
        if (tid < s) sh->spart[tid] += sh->spart[tid + s];
        __syncthreads();
    }
    if (tid == 0) g_dist[b] = sh->spart[0];

    // ---------------- last block reduces g_dist -> out ----------------
    __threadfence();
    if (tid == 0) sh->tick = atomicAdd(&g_count, 1u);
    __syncthreads();
    if (sh->tick == NB - 1) {
        __threadfence();
        sh->spart[tid] = g_dist[tid];
        __syncthreads();
        #pragma unroll
        for (int s = 128; s; s >>= 1) {
            if (tid < s) sh->spart[tid] += sh->spart[tid + s];
            __syncthreads();
        }
        if (tid == 0) {
            out[0] = 0.01f * sh->spart[0];
            g_count = 0;   // reset for next (graph-replayed) call
        }
    }
}

extern "C" void kernel_launch(void* const* d_in, const int* in_sizes, int n_in,
                              void* d_out, int out_size) {
    const float* txt = (const float*)d_in[0];   // entitytxt_vec [256,128,1024] f32
    const float* obj = (const float*)d_in[1];   // object_vec    [256,128,1024] f32
    const int*   tn  = (const int*)d_in[2];     // entitytxt_num [256,128] i32
    const int*   on  = (const int*)d_in[3];     // object_num    [256,128] i32

    size_t shbytes = sizeof(ShMem);
    cudaFuncSetAttribute(ot_kernel, cudaFuncAttributeMaxDynamicSharedMemorySize,
                         (int)shbytes);
    ot_kernel<<<NB, NTHREADS, shbytes>>>(txt, obj, tn, on, (float*)d_out);
}

// round 13
// speedup vs baseline: 1.2269x; 1.2269x over previous
#include <cuda_runtime.h>
#include <cuda_bf16.h>
#include <cstdint>

#define NB 256      // batch
#define M 128       // txt positions (j), compacted to NJ real
#define N 128       // img positions (i), compacted to NI real
#define D 1024      // embedding dim
#define NTHREADS 256
#define KBLK 32                   // k-values per tile block (32 bf16 = 64B row)
#define NBLKS (D / KBLK)          // 32
#define TILE_B (128 * 64)         // 8KB per matrix per buffer

typedef unsigned long long u64;

__device__ float g_dist[NB];
__device__ unsigned int g_count = 0;

// ------------------------- helpers -------------------------
__device__ __forceinline__ uint32_t smem_u32(const void* p) {
    uint32_t a;
    asm("{ .reg .u64 t; cvta.to.shared.u64 t, %1; cvt.u32.u64 %0, t; }"
        : "=r"(a) : "l"(p));
    return a;
}
#define SWZ64(o) ((o) ^ ((((uint32_t)(o)) >> 3) & 0x30))

__device__ __forceinline__ uint32_t cvt2(float a, float b) {
    __nv_bfloat162 p = __float22bfloat162_rn(make_float2(a, b));
    return *reinterpret_cast<uint32_t*>(&p);
}
__device__ __forceinline__ float fast_exp(float x) {
    float y;
    asm("ex2.approx.f32 %0, %1;" : "=f"(y) : "f"(x * 1.4426950408889634f));
    return y;
}
__device__ __forceinline__ float frcp(float x) {
    float y;
    asm("rcp.approx.f32 %0, %1;" : "=f"(y) : "f"(x));
    return y;
}
__device__ __forceinline__ float frsq(float x) {
    float y;
    asm("rsqrt.approx.f32 %0, %1;" : "=f"(y) : "f"(x));
    return y;
}
__device__ __forceinline__ void ldsm_x4(uint32_t addr, uint32_t& r0, uint32_t& r1,
                                        uint32_t& r2, uint32_t& r3) {
    asm volatile("ldmatrix.sync.aligned.m8n8.x4.shared.b16 {%0,%1,%2,%3}, [%4];"
                 : "=r"(r0), "=r"(r1), "=r"(r2), "=r"(r3) : "r"(addr));
}
__device__ __forceinline__ void mma16816(float* c, uint32_t a0, uint32_t a1,
                                         uint32_t a2, uint32_t a3,
                                         uint32_t b0, uint32_t b1) {
    asm volatile(
        "mma.sync.aligned.m16n8k16.row.col.f32.bf16.bf16.f32 "
        "{%0,%1,%2,%3}, {%4,%5,%6,%7}, {%8,%9}, {%0,%1,%2,%3};"
        : "+f"(c[0]), "+f"(c[1]), "+f"(c[2]), "+f"(c[3])
        : "r"(a0), "r"(a1), "r"(a2), "r"(a3), "r"(b0), "r"(b1));
}

// ---- packed f32x2 (sm_100+ base ISA) ----
__device__ __forceinline__ u64 pack2(float x, float y) {
    u64 r; asm("mov.b64 %0, {%1, %2};" : "=l"(r) : "f"(x), "f"(y)); return r;
}
__device__ __forceinline__ float2 unpack2(u64 v) {
    float2 r; asm("mov.b64 {%0, %1}, %2;" : "=f"(r.x), "=f"(r.y) : "l"(v)); return r;
}
__device__ __forceinline__ u64 mul2(u64 a, u64 b) {
    u64 d; asm("mul.rn.f32x2 %0, %1, %2;" : "=l"(d) : "l"(a), "l"(b)); return d;
}
__device__ __forceinline__ u64 fma2_(u64 a, u64 b, u64 c) {
    u64 d; asm("fma.rn.f32x2 %0, %1, %2, %3;" : "=l"(d) : "l"(a), "l"(b), "l"(c)); return d;
}

union F4U2 { float4 f4; u64 u2[2]; };

// ownership-linear index (floats): thread (warp w, lane = jg + 16*ig)
// owns i = 2*w + ig + 16*ii (ii=0..7), j = jg*8 .. jg*8+7 (half = (j>>2)&1)
#define AIDX(w, ii, half, ig, jg) \
    ((((((w) * 8 + (ii)) * 2 + (half)) * 2 + (ig)) * 16 + (jg)) * 4)

struct ShMem {
    float As[N * M];        // 64KB ownership-linear A; GEMM k-tiles aliased inside
    float spartW[8][128];   // per-warp s_j partials
    float spart[NTHREADS];
    float invx[M];
    float invy[N];
    float xmask[M];
    float sigma[M];
    int   idxj[M];
    int   idxi[N];
    int   NJ, NI;
    unsigned int tick;
};

extern __shared__ __align__(16) char smem_raw[];

__global__ __launch_bounds__(NTHREADS, 2)
void ot_kernel(const float* __restrict__ txt,
               const float* __restrict__ obj,
               const int* __restrict__ txt_num,
               const int* __restrict__ obj_num,
               float* __restrict__ out)
{
    ShMem* sh = reinterpret_cast<ShMem*>(smem_raw);
    const int tid  = threadIdx.x;
    const int lane = tid & 31;
    const int warp = tid >> 5;
    const int b    = blockIdx.x;

    const float* txt_b = txt + (size_t)b * M * D;
    const float* obj_b = obj + (size_t)b * M * D;

    // GEMM tiles aliased into the (not-yet-used) As region, 1024-aligned
    char* tbase = (char*)(((uintptr_t)sh->As + 1023) & ~(uintptr_t)1023);
    const uint32_t tbase_s = (smem_u32(sh->As) + 1023u) & ~1023u;

    // ---------------- Phase 0: compaction (ballot ranks) ----------------
    if (warp == 0) {
        int base = 0;
        #pragma unroll
        for (int c = 0; c < 4; ++c) {
            int j = c * 32 + lane;
            bool real = (txt_num[b * 128 + j] != 0);
            unsigned m = __ballot_sync(0xffffffffu, real);
            int rank = base + __popc(m & ((1u << lane) - 1u));
            if (real) sh->idxj[rank] = j;
            base += __popc(m);
        }
        if (lane == 0) sh->NJ = base;
    }
    if (warp == 1) {
        int base = 0;
        #pragma unroll
        for (int c = 0; c < 4; ++c) {
            int i = c * 32 + lane;
            bool real = (i < 127) && (obj_num[b * 128 + i + 1] != 0);
            unsigned m = __ballot_sync(0xffffffffu, real);
            int rank = base + __popc(m & ((1u << lane) - 1u));
            if (real) sh->idxi[rank] = i;
            base += __popc(m);
        }
        if (lane == 0) sh->NI = base;
    }
    __syncthreads();
    const int NJ = sh->NJ, NI = sh->NI;
    const float xlv = (float)NJ, ylv = (float)NI;
    if (tid < 128) sh->xmask[tid] = (tid < NJ) ? 0.f : 1e4f;

    // ---------------- Phase 1: GEMM via mma.sync bf16 (compact rows) --------
    const int row  = tid >> 1;
    const int half = tid & 1;
    const bool xreal = (row < NJ);
    const bool yreal = (row < NI);
    const float* xsrc0 = xreal ? (txt_b + (size_t)sh->idxj[row] * D + half * 16) : txt_b;
    const float* ysrc0 = yreal ? (obj_b + (size_t)(sh->idxi[row] + 1) * D + half * 16) : obj_b;
    const uint32_t st_off = (uint32_t)(row * 64 + half * 32);
    float ssx = 0.f, ssy = 0.f;

    // Adaptive MMA tiling: 4 (it) x 2 (jt) warp grid over TI x TJ tiles sized
    // to the compacted problem -> typical case all 8 warps own one live tile.
    const int TI = (NI > 64) ? 32 : 16;
    const int TJ = (NJ > 64) ? 64 : 32;
    const int MIn = TI >> 4;        // 1 or 2
    const int NBn = TJ >> 4;        // 2 or 4
    const int it = warp >> 1;
    const int jt = warp & 1;
    const int ib_m = it * TI;
    const int jb_m = jt * TJ;
    const bool mma_act = (ib_m < NI) && (jb_m < NJ);

    float acc[2][4][2][4];
    #pragma unroll
    for (int mi = 0; mi < 2; ++mi)
        #pragma unroll
        for (int nb = 0; nb < 4; ++nb)
            #pragma unroll
            for (int q = 0; q < 2; ++q)
                #pragma unroll
                for (int c = 0; c < 4; ++c) acc[mi][nb][q][c] = 0.f;

    const uint32_t ro = (lane & 7) + (((lane >> 3) & 1) << 3);
    const uint32_t ch = (lane >> 4) << 4;

    float4 vx[4], vy[4];
    if (xreal) {
        const float4* sx = reinterpret_cast<const float4*>(xsrc0);
        #pragma unroll
        for (int q = 0; q < 4; ++q) vx[q] = sx[q];
    }
    if (yreal) {
        const float4* sy = reinterpret_cast<const float4*>(ysrc0);
        #pragma unroll
        for (int q = 0; q < 4; ++q) vy[q] = sy[q];
    }

    for (int blk = 0; blk < NBLKS; ++blk) {
        const int buf = blk & 1;
        char* xt = tbase + buf * (2 * TILE_B);
        char* yt = xt + TILE_B;

        if (xreal) {
            #pragma unroll
            for (int q = 0; q < 4; ++q)
                ssx += vx[q].x * vx[q].x + vx[q].y * vx[q].y
                     + vx[q].z * vx[q].z + vx[q].w * vx[q].w;
            uint4 u0 = make_uint4(cvt2(vx[0].x, vx[0].y), cvt2(vx[0].z, vx[0].w),
                                  cvt2(vx[1].x, vx[1].y), cvt2(vx[1].z, vx[1].w));
            uint4 u1 = make_uint4(cvt2(vx[2].x, vx[2].y), cvt2(vx[2].z, vx[2].w),
                                  cvt2(vx[3].x, vx[3].y), cvt2(vx[3].z, vx[3].w));
            *reinterpret_cast<uint4*>(xt + SWZ64(st_off))      = u0;
            *reinterpret_cast<uint4*>(xt + SWZ64(st_off + 16)) = u1;
        }
        if (yreal) {
            #pragma unroll
            for (int q = 0; q < 4; ++q)
                ssy += vy[q].x * vy[q].x + vy[q].y * vy[q].y
                     + vy[q].z * vy[q].z + vy[q].w * vy[q].w;
            uint4 w0 = make_uint4(cvt2(vy[0].x, vy[0].y), cvt2(vy[0].z, vy[0].w),
                                  cvt2(vy[1].x, vy[1].y), cvt2(vy[1].z, vy[1].w));
            uint4 w1 = make_uint4(cvt2(vy[2].x, vy[2].y), cvt2(vy[2].z, vy[2].w),
                                  cvt2(vy[3].x, vy[3].y), cvt2(vy[3].z, vy[3].w));
            *reinterpret_cast<uint4*>(yt + SWZ64(st_off))      = w0;
            *reinterpret_cast<uint4*>(yt + SWZ64(st_off + 16)) = w1;
        }
        // prefetch next block before the barrier (overlaps with MMA)
        if (blk + 1 < NBLKS) {
            if (xreal) {
                const float4* sx = reinterpret_cast<const float4*>(xsrc0 + (blk + 1) * KBLK);
                #pragma unroll
                for (int q = 0; q < 4; ++q) vx[q] = sx[q];
            }
            if (yreal) {
                const float4* sy = reinterpret_cast<const float4*>(ysrc0 + (blk + 1) * KBLK);
                #pragma unroll
                for (int q = 0; q < 4; ++q) vy[q] = sy[q];
            }
        }
        __syncthreads();   // single barrier per block (buffer reuse distance = 2)

        if (mma_act) {
            const uint32_t xs = tbase_s + buf * (2 * TILE_B);
            const uint32_t ys = xs + TILE_B;
            #pragma unroll
            for (int s = 0; s < 2; ++s) {
                const uint32_t coff = (uint32_t)(s * 32) + ch;
                uint32_t a[2][4];
                #pragma unroll
                for (int mi = 0; mi < 2; ++mi)
                    if (mi < MIn && ib_m + mi * 16 < NI)
                        ldsm_x4(ys + SWZ64((ib_m + mi * 16 + ro) * 64 + coff),
                                a[mi][0], a[mi][1], a[mi][2], a[mi][3]);
                #pragma unroll
                for (int nb = 0; nb < 4; ++nb) {
                    if (nb < NBn && jb_m + nb * 16 < NJ) {
                        uint32_t r0, r1, r2, r3;
                        ldsm_x4(xs + SWZ64((jb_m + nb * 16 + ro) * 64 + coff),
                                r0, r1, r2, r3);
                        #pragma unroll
                        for (int mi = 0; mi < 2; ++mi) {
                            if (mi < MIn && ib_m + mi * 16 < NI) {
                                mma16816(acc[mi][nb][0], a[mi][0], a[mi][1], a[mi][2], a[mi][3], r0, r2);
                                mma16816(acc[mi][nb][1], a[mi][0], a[mi][1], a[mi][2], a[mi][3], r1, r3);
                            }
                        }
                    }
                }
            }
        }
    }
    __syncthreads();

    // ---------------- zero As (uncovered tiles must read as 0) --------------
    {
        uint4 z4 = make_uint4(0u, 0u, 0u, 0u);
        uint4* a4 = reinterpret_cast<uint4*>(sh->As);
        #pragma unroll
        for (int k = 0; k < 16; ++k) a4[tid + 256 * k] = z4;
    }

    // ---------------- norms ----------------
    sh->spart[tid] = ssx;
    __syncthreads();
    if (tid < 128)
        sh->invx[tid] = frsq(fmaxf(sh->spart[2 * tid] + sh->spart[2 * tid + 1], 1e-10f));
    __syncthreads();
    sh->spart[tid] = ssy;
    __syncthreads();
    if (tid < 128)
        sh->invy[tid] = frsq(fmaxf(sh->spart[2 * tid] + sh->spart[2 * tid + 1], 1e-10f));
    __syncthreads();

    // ---------------- Epilogue: acc -> As (strided ownership layout) --------
    {
        const int r_ = lane >> 2;           // 0..7 = i mod 16 (low 8)
        const int cp = (lane & 3) * 2;
        const int w_e  = r_ >> 1;
        const int ig_e = r_ & 1;
        #pragma unroll
        for (int mi = 0; mi < 2; ++mi) {
            if (mi < MIn && ib_m + mi * 16 < NI && jb_m < NJ) {
                const int i0 = ib_m + mi * 16 + r_;
                const int i1 = i0 + 8;
                const int ii_e = i0 >> 4;
                const float iy0 = sh->invy[i0], iy1 = sh->invy[i1];
                #pragma unroll
                for (int nb = 0; nb < 4; ++nb) {
                    if (nb < NBn && jb_m + nb * 16 < NJ) {
                        #pragma unroll
                        for (int q = 0; q < 2; ++q) {
                            const int j = jb_m + nb * 16 + q * 8 + cp;
                            const int jge = j >> 3, hfe = (j >> 2) & 1, ue = j & 3;
                            const float ix0 = sh->invx[j], ix1 = sh->invx[j + 1];
                            const float* c = acc[mi][nb][q];
                            float a00 = (i0 < NI && j     < NJ)
                                      ? fast_exp(-2.f * (1.f - c[0] * iy0 * ix0)) : 0.f;
                            float a01 = (i0 < NI && j + 1 < NJ)
                                      ? fast_exp(-2.f * (1.f - c[1] * iy0 * ix1)) : 0.f;
                            float a10 = (i1 < NI && j     < NJ)
                                      ? fast_exp(-2.f * (1.f - c[2] * iy1 * ix0)) : 0.f;
                            float a11 = (i1 < NI && j + 1 < NJ)
                                      ? fast_exp(-2.f * (1.f - c[3] * iy1 * ix1)) : 0.f;
                            *reinterpret_cast<float2*>(&sh->As[AIDX(w_e,     ii_e, hfe, ig_e, jge) + ue])
                                = make_float2(a00, a01);
                            *reinterpret_cast<float2*>(&sh->As[AIDX(w_e + 4, ii_e, hfe, ig_e, jge) + ue])
                                = make_float2(a10, a11);
                        }
                    }
                }
            }
        }
    }
    __syncthreads();

    // ---------------- Phase 2: IPOT, Q in regs, rows strided over all warps --
    const int jg = lane & 15;
    const int ig = lane >> 4;
    const int ibase = 2 * warp + ig;   // this thread's rows: ibase + 16*ii

    u64 q2[8][4];
    float ym_[8], d_[8];
    #pragma unroll
    for (int ii = 0; ii < 8; ++ii) {
        ym_[ii] = (ibase + 16 * ii < NI) ? 0.f : 1e4f;
        d_[ii] = 0.f;
        if (2 * warp + 16 * ii < NI) {   // warp-uniform liveness
            F4U2 u0, u1;
            u0.f4 = *reinterpret_cast<const float4*>(&sh->As[AIDX(warp, ii, 0, ig, jg)]);
            u1.f4 = *reinterpret_cast<const float4*>(&sh->As[AIDX(warp, ii, 1, ig, jg)]);
            q2[ii][0] = u0.u2[0]; q2[ii][1] = u0.u2[1];
            q2[ii][2] = u1.u2[0]; q2[ii][3] = u1.u2[1];
        } else {
            q2[ii][0] = q2[ii][1] = q2[ii][2] = q2[ii][3] = 0ull;
        }
    }

    if (tid < 128) sh->sigma[tid] = (tid < NJ) ? frcp(xlv) : 0.f;
    __syncthreads();

    u64 sg2[4];
    {
        F4U2 sa, sb;
        sa.f4 = *reinterpret_cast<const float4*>(&sh->sigma[jg * 8]);
        sb.f4 = *reinterpret_cast<const float4*>(&sh->sigma[jg * 8 + 4]);
        sg2[0] = sa.u2[0]; sg2[1] = sa.u2[1]; sg2[2] = sb.u2[0]; sg2[3] = sb.u2[1];
    }

    // delta_0 and fused s_j partials from Q = A, sigma_0
    u64 s2[4];
    #pragma unroll
    for (int p = 0; p < 4; ++p) s2[p] = pack2(0.f, 0.f);
    #pragma unroll
    for (int ii = 0; ii < 8; ++ii) {
        if (2 * warp + 16 * ii < NI) {
            u64 acc2 = mul2(q2[ii][0], sg2[0]);
            acc2 = fma2_(q2[ii][1], sg2[1], acc2);
            acc2 = fma2_(q2[ii][2], sg2[2], acc2);
            acc2 = fma2_(q2[ii][3], sg2[3], acc2);
            float2 pr = unpack2(acc2);
            float rv = pr.x + pr.y;
            #pragma unroll
            for (int o = 1; o < 16; o <<= 1) rv += __shfl_xor_sync(0xffffffffu, rv, o);
            d_[ii] = frcp(ylv * rv + ym_[ii]);
            u64 dd = pack2(d_[ii], d_[ii]);
            #pragma unroll
            for (int p = 0; p < 4; ++p) s2[p] = fma2_(q2[ii][p], dd, s2[p]);
        }
    }

    for (int t = 0; t < 50; ++t) {
        // reduce fused s_j partials across the warp, publish per-warp
        float s8[8];
        #pragma unroll
        for (int p = 0; p < 4; ++p) {
            float2 v = unpack2(s2[p]);
            s8[2 * p] = v.x; s8[2 * p + 1] = v.y;
        }
        #pragma unroll
        for (int e = 0; e < 8; ++e) s8[e] += __shfl_xor_sync(0xffffffffu, s8[e], 16);
        if (ig == 0) {
            *reinterpret_cast<float4*>(&sh->spartW[warp][jg * 8])
                = make_float4(s8[0], s8[1], s8[2], s8[3]);
            *reinterpret_cast<float4*>(&sh->spartW[warp][jg * 8 + 4])
                = make_float4(s8[4], s8[5], s8[6], s8[7]);
        }
        __syncthreads();
        if (tid < 128) {
            float s = 0.f;
            #pragma unroll
            for (int w8 = 0; w8 < 8; ++w8) s += sh->spartW[w8][tid];
            sh->sigma[tid] = frcp(xlv * s + sh->xmask[tid]);
        }
        __syncthreads();
        {
            F4U2 sa, sb;
            sa.f4 = *reinterpret_cast<const float4*>(&sh->sigma[jg * 8]);
            sb.f4 = *reinterpret_cast<const float4*>(&sh->sigma[jg * 8 + 4]);
            sg2[0] = sa.u2[0]; sg2[1] = sa.u2[1]; sg2[2] = sb.u2[0]; sg2[3] = sb.u2[1];
        }
        if (t < 49) {
            // Q <- A*delta*Q*sigma, fused with next r_i -> delta -> s_j partials
            #pragma unroll
            for (int p = 0; p < 4; ++p) s2[p] = pack2(0.f, 0.f);
            #pragma unroll
            for (int ii = 0; ii < 8; ++ii) {
                if (2 * warp + 16 * ii < NI) {
                    F4U2 a0, a1;
                    a0.f4 = *reinterpret_cast<const float4*>(&sh->As[AIDX(warp, ii, 0, ig, jg)]);
                    a1.f4 = *reinterpret_cast<const float4*>(&sh->As[AIDX(warp, ii, 1, ig, jg)]);
                    u64 av[4] = {a0.u2[0], a0.u2[1], a1.u2[0], a1.u2[1]};
                    u64 dd = pack2(d_[ii], d_[ii]);
                    u64 acc2 = pack2(0.f, 0.f);
                    #pragma unroll
                    for (int p = 0; p < 4; ++p) {
                        u64 f  = mul2(sg2[p], dd);
                        u64 tq = mul2(av[p], q2[ii][p]);
                        q2[ii][p] = mul2(tq, f);
                        acc2 = fma2_(q2[ii][p], sg2[p], acc2);
                    }
                    float2 pr = unpack2(acc2);
                    float rv = pr.x + pr.y;
                    #pragma unroll
                    for (int o = 1; o < 16; o <<= 1) rv += __shfl_xor_sync(0xffffffffu, rv, o);
                    d_[ii] = frcp(ylv * rv + ym_[ii]);
                    u64 ddn = pack2(d_[ii], d_[ii]);
                    #pragma unroll
                    for (int p = 0; p < 4; ++p) s2[p] = fma2_(q2[ii][p], ddn, s2[p]);
                }
            }
        }
    }

    // ---------------- Final: dist_b = sum cost * delta_i * Q * sigma_j --------
    float local = 0.f;
    #pragma unroll
    for (int ii = 0; ii < 8; ++ii) {
        if (2 * warp + 16 * ii < NI) {
            F4U2 a0, a1;
            a0.f4 = *reinterpret_cast<const float4*>(&sh->As[AIDX(warp, ii, 0, ig, jg)]);
            a1.f4 = *reinterpret_cast<const float4*>(&sh->As[AIDX(warp, ii, 1, ig, jg)]);
            u64 av[4] = {a0.u2[0], a0.u2[1], a1.u2[0], a1.u2[1]};
            const float dl = d_[ii];
            #pragma unroll
            for (int p = 0; p < 4; ++p) {
                float2 aa = unpack2(av[p]);
                float2 qq = unpack2(q2[ii][p]);
                float2 ss = unpack2(sg2[p]);
                if (aa.x > 0.f) local += (-0.5f * __logf(aa.x)) * dl * qq.x * ss.x;
                if (aa.y > 0.f) local += (-0.5f * __logf(aa.y)) * dl * qq.y * ss.y;
            }
        }
    }
    __syncthreads();
    sh->spart[tid] = local;
    __syncthreads();
    #pragma unroll
    for (int s = 128; s; s >>= 1) {
        if (tid < s) sh->spart[tid] += sh->spart[tid + s];
        __syncthreads();
    }
    if (tid == 0) g_dist[b] = sh->spart[0];

    // ---------------- last block reduces g_dist -> out ----------------
    __threadfence();
    if (tid == 0) sh->tick = atomicAdd(&g_count, 1u);
    __syncthreads();
    if (sh->tick == NB - 1) {
        __threadfence();
        sh->spart[tid] = g_dist[tid];
        __syncthreads();
        #pragma unroll
        for (int s = 128; s; s >>= 1) {
            if (tid < s) sh->spart[tid] += sh->spart[tid + s];
            __syncthreads();
        }
        if (tid == 0) {
            out[0] = 0.01f * sh->spart[0];
            g_count = 0;   // reset for next (graph-replayed) call
        }
    }
}

extern "C" void kernel_launch(void* const* d_in, const int* in_sizes, int n_in,
                              void* d_out, int out_size) {
    const float* txt = (const float*)d_in[0];   // entitytxt_vec [256,128,1024] f32
    const float* obj = (const float*)d_in[1];   // object_vec    [256,128,1024] f32
    const int*   tn  = (const int*)d_in[2];     // entitytxt_num [256,128] i32
    const int*   on  = (const int*)d_in[3];     // object_num    [256,128] i32

    size_t shbytes = sizeof(ShMem);
    cudaFuncSetAttribute(ot_kernel, cudaFuncAttributeMaxDynamicSharedMemorySize,
                         (int)shbytes);
    ot_kernel<<<NB, NTHREADS, shbytes>>>(txt, obj, tn, on, (float*)d_out);
}